// round 4
// baseline (speedup 1.0000x reference)
#include <cuda_runtime.h>

// Problem constants (static per reference)
#define NIMG 8
#define CINC 64
#define HH   112
#define WW   112
#define NP   (HH*WW)      // 12544 pixels/patches per image
#define NP4  (NP/4)       // 3136 float4 groups per image
#define COUTC 64
#define DD   576          // CIN*K*K
#define MEM  1025
#define CG   8            // channels per thread in output phase

#define NBLK 296          // 2 blocks per SM on 148 SMs -> guaranteed co-resident
#define NTHR 256
#define NTOT (NBLK*NTHR)

// Scratch (device globals — no allocation allowed)
__device__ float d_S[NIMG*NP];               // per-pixel channel sums
__device__ int   d_bins[NIMG*NP];            // bin per patch
__device__ int   d_first[NIMG*MEM];          // first-occurring patch idx per bin
__device__ float d_rep_t[NIMG*COUTC*MEM];    // representative outputs, [n][c][bin]
__device__ float d_Wt[DD*COUTC];             // transposed weight: Wt[d*64 + c]
__device__ unsigned int d_barc[4];           // grid-barrier counters (zero-init; self-resetting)

// Grid-wide barrier: monotonic counter per barrier, spin until all arrive.
__device__ __forceinline__ void gsync(int idx) {
    __syncthreads();
    if (threadIdx.x == 0) {
        __threadfence();
        atomicAdd(&d_barc[idx], 1u);
        while (*(volatile unsigned int*)&d_barc[idx] < (unsigned int)NBLK) { }
        __threadfence();
    }
    __syncthreads();
}

__global__ void __launch_bounds__(NTHR, 2)
k_fused(const float* __restrict__ fmap,
        const float* __restrict__ weight,
        const float* __restrict__ bias,
        float* __restrict__ out) {
    const int gtid = blockIdx.x * NTHR + threadIdx.x;

    // ---------------- Phase A: channel sums + first-init + weight transpose ----
    for (int i = gtid; i < NIMG*MEM; i += NTOT) d_first[i] = NP;

    for (int i = gtid; i < COUTC*DD; i += NTOT) {
        int c = i / DD, d = i - c*DD;
        d_Wt[d*COUTC + c] = weight[i];
    }

    for (int i = gtid; i < NIMG*NP4; i += NTOT) {
        int n = i / NP4, q = i - n*NP4;
        const float4* base = (const float4*)(fmap + (size_t)n * CINC * NP) + q;
        float4 s = make_float4(0.f, 0.f, 0.f, 0.f);
        #pragma unroll 8
        for (int c = 0; c < CINC; c++) {
            float4 v = base[c * NP4];
            s.x += v.x; s.y += v.y; s.z += v.z; s.w += v.w;
        }
        ((float4*)d_S)[i] = s;
    }

    gsync(0);

    // ---------------- Phase B: 3x3 box sum -> bin -> scatter-min first ---------
    for (int i = gtid; i < NIMG*NP4; i += NTOT) {
        int n = i / NP4, q = i - n*NP4;
        int p0 = q * 4;
        int h = p0 / WW, w0 = p0 - h*WW;
        const float* S = d_S + n*NP;

        float a0 = 0.f, a1 = 0.f, a2 = 0.f, a3 = 0.f;
        #pragma unroll
        for (int dy = -1; dy <= 1; dy++) {
            int y = h + dy;
            if (y < 0 || y >= HH) continue;
            const float* Sy = S + y*WW;
            float  left  = (w0 > 0)      ? Sy[w0 - 1] : 0.f;
            float4 mid   = *(const float4*)(Sy + w0);
            float  right = (w0 + 4 < WW) ? Sy[w0 + 4] : 0.f;
            a0 += left  + mid.x + mid.y;
            a1 += mid.x + mid.y + mid.z;
            a2 += mid.y + mid.z + mid.w;
            a3 += mid.z + mid.w + right;
        }

        int4 b4;
        {
            float m; int s, b;
            m = a0 / (float)DD; s = (int)(m * 100.0f); b = s + 512;
            b4.x = b < 0 ? 0 : (b > MEM-1 ? MEM-1 : b);
            m = a1 / (float)DD; s = (int)(m * 100.0f); b = s + 512;
            b4.y = b < 0 ? 0 : (b > MEM-1 ? MEM-1 : b);
            m = a2 / (float)DD; s = (int)(m * 100.0f); b = s + 512;
            b4.z = b < 0 ? 0 : (b > MEM-1 ? MEM-1 : b);
            m = a3 / (float)DD; s = (int)(m * 100.0f); b = s + 512;
            b4.w = b < 0 ? 0 : (b > MEM-1 ? MEM-1 : b);
        }
        ((int4*)d_bins)[i] = b4;

        int base = n*MEM;
        atomicMin(&d_first[base + b4.x], p0 + 0);
        atomicMin(&d_first[base + b4.y], p0 + 1);
        atomicMin(&d_first[base + b4.z], p0 + 2);
        atomicMin(&d_first[base + b4.w], p0 + 3);
    }

    gsync(1);

    // ---------------- Phase C: representative GEMVs ----------------------------
    {
        __shared__ float sh[DD];
        for (int pair = blockIdx.x; pair < NIMG*MEM; pair += NBLK) {
            int p = d_first[pair];              // block-uniform
            if (p >= NP) continue;              // unused bin (uniform branch)
            int n = pair / MEM, b = pair - n*MEM;
            int h = p / WW, w = p - h*WW;

            __syncthreads();                    // protect sh reuse across pairs
            for (int d = threadIdx.x; d < DD; d += NTHR) {
                int cin = d / 9, r = d - cin*9;
                int kh = r / 3, kw = r - kh*3;
                int y = h + kh - 1, x = w + kw - 1;
                float v = 0.f;
                if (y >= 0 && y < HH && x >= 0 && x < WW)
                    v = fmap[(((size_t)n*CINC + cin)*HH + y)*WW + x];
                sh[d] = v;
            }
            __syncthreads();

            if (threadIdx.x < COUTC) {
                int t = threadIdx.x;
                float acc = bias[t];
                #pragma unroll 8
                for (int d = 0; d < DD; d++)
                    acc = fmaf(sh[d], d_Wt[d*COUTC + t], acc);
                d_rep_t[((size_t)n*COUTC + t)*MEM + b] = acc;
            }
        }
    }

    gsync(2);

    // ---------------- Phase D: gather + write output ---------------------------
    for (int i = gtid; i < NIMG*(COUTC/CG)*NP4; i += NTOT) {
        int q    = i % NP4;
        int rest = i / NP4;
        int cg   = rest % (COUTC/CG);
        int n    = rest / (COUTC/CG);
        int c0   = cg * CG;

        int4 b4 = ((const int4*)d_bins)[n*NP4 + q];

        #pragma unroll
        for (int j = 0; j < CG; j++) {
            const float* rt = d_rep_t + ((size_t)n*COUTC + (c0 + j))*MEM;
            float4 o;
            o.x = rt[b4.x];
            o.y = rt[b4.y];
            o.z = rt[b4.z];
            o.w = rt[b4.w];
            ((float4*)out)[((size_t)n*COUTC + (c0 + j))*NP4 + q] = o;
        }
    }

    // ---------------- Final arrival: last block resets barrier counters --------
    __syncthreads();
    if (threadIdx.x == 0) {
        __threadfence();
        unsigned int prev = atomicAdd(&d_barc[3], 1u);
        if (prev == (unsigned int)(NBLK - 1)) {
            d_barc[0] = 0; d_barc[1] = 0; d_barc[2] = 0; d_barc[3] = 0;
            __threadfence();
        }
    }
}

extern "C" void kernel_launch(void* const* d_in, const int* in_sizes, int n_in,
                              void* d_out, int out_size) {
    const float* fmap   = (const float*)d_in[0];
    const float* weight = (const float*)d_in[1];
    const float* bias   = (const float*)d_in[2];
    float* out = (float*)d_out;

    (void)in_sizes; (void)n_in; (void)out_size;

    k_fused<<<NBLK, NTHR>>>(fmap, weight, bias, out);
}

// round 5
// speedup vs baseline: 2.2331x; 2.2331x over previous
#include <cuda_runtime.h>

// Problem constants (static per reference)
#define NIMG 8
#define CINC 64
#define HH   112
#define WW   112
#define NP   (HH*WW)      // 12544 pixels/patches per image
#define NP4  (NP/4)       // 3136 float4 groups per image
#define COUTC 64
#define DD   576          // CIN*K*K
#define MEM  1025
#define CG   8            // channels per thread in output phase

// Scratch (device globals — no allocation allowed)
__device__ float d_S[NIMG*NP];                 // per-pixel channel sums
__device__ int   d_bins[NIMG*NP];              // bin per patch
__device__ int   d_first[NIMG*MEM];            // first-occurring patch idx per bin
__device__ float d_rep4[NIMG*(COUTC/4)*MEM*4]; // reps, quad layout: [n][c/4][bin][c%4]
__device__ float d_Wt[DD*COUTC];               // transposed weight: Wt[d*64 + c]

// K1: channel sums (float4, 4 px/thread) + init first table + weight transpose.
// FP accumulation order identical to validated R1/R2 (zero bin flips).
__global__ void k_prep(const float* __restrict__ fmap,
                       const float* __restrict__ weight) {
    int tid   = blockIdx.x * blockDim.x + threadIdx.x;   // [0, NIMG*NP4)
    int total = gridDim.x * blockDim.x;

    for (int i = tid; i < NIMG*MEM; i += total) d_first[i] = NP;

    for (int i = tid; i < COUTC*DD; i += total) {
        int c = i / DD, d = i - c*DD;
        d_Wt[d*COUTC + c] = weight[i];
    }

    int n = tid / NP4, q = tid - n*NP4;
    const float4* base = (const float4*)(fmap + (size_t)n * CINC * NP) + q;
    float4 s = make_float4(0.f, 0.f, 0.f, 0.f);
    #pragma unroll 8
    for (int c = 0; c < CINC; c++) {
        float4 v = base[c * NP4];
        s.x += v.x; s.y += v.y; s.z += v.z; s.w += v.w;
    }
    ((float4*)d_S)[tid] = s;
}

// K2: 3x3 box sum (zero-padded) -> quantized bin -> scatter-min first occurrence.
__global__ void k_bin() {
    int tid = blockIdx.x * blockDim.x + threadIdx.x;     // [0, NIMG*NP4)
    int n = tid / NP4, q = tid - n*NP4;
    int p0 = q * 4;
    int h = p0 / WW, w0 = p0 - h*WW;
    const float* S = d_S + n*NP;

    float a0 = 0.f, a1 = 0.f, a2 = 0.f, a3 = 0.f;
    #pragma unroll
    for (int dy = -1; dy <= 1; dy++) {
        int y = h + dy;
        if (y < 0 || y >= HH) continue;
        const float* Sy = S + y*WW;
        float  left  = (w0 > 0)      ? Sy[w0 - 1] : 0.f;
        float4 mid   = *(const float4*)(Sy + w0);
        float  right = (w0 + 4 < WW) ? Sy[w0 + 4] : 0.f;
        a0 += left  + mid.x + mid.y;
        a1 += mid.x + mid.y + mid.z;
        a2 += mid.y + mid.z + mid.w;
        a3 += mid.z + mid.w + right;
    }

    int4 b4;
    {
        float m; int s, b;
        m = a0 / (float)DD; s = (int)(m * 100.0f); b = s + 512;
        b4.x = b < 0 ? 0 : (b > MEM-1 ? MEM-1 : b);
        m = a1 / (float)DD; s = (int)(m * 100.0f); b = s + 512;
        b4.y = b < 0 ? 0 : (b > MEM-1 ? MEM-1 : b);
        m = a2 / (float)DD; s = (int)(m * 100.0f); b = s + 512;
        b4.z = b < 0 ? 0 : (b > MEM-1 ? MEM-1 : b);
        m = a3 / (float)DD; s = (int)(m * 100.0f); b = s + 512;
        b4.w = b < 0 ? 0 : (b > MEM-1 ? MEM-1 : b);
    }
    ((int4*)d_bins)[tid] = b4;

    int base = n*MEM;
    atomicMin(&d_first[base + b4.x], p0 + 0);
    atomicMin(&d_first[base + b4.y], p0 + 1);
    atomicMin(&d_first[base + b4.z], p0 + 2);
    atomicMin(&d_first[base + b4.w], p0 + 3);
}

// K3: representative GEMVs, split-K. One block per (bin, image), 512 threads =
// 64 channels x 8 d-groups of 72. Only populated bins (~35/image) do work.
__global__ void __launch_bounds__(512) k_rep(const float* __restrict__ fmap,
                                             const float* __restrict__ bias) {
    int b = blockIdx.x, n = blockIdx.y;
    int p = d_first[n*MEM + b];
    if (p >= NP) return;                   // unused bin

    __shared__ float sh[DD];
    __shared__ float red[512];
    int t = threadIdx.x;
    int h = p / WW, w = p - h*WW;

    for (int d = t; d < DD; d += 512) {
        int cin = d / 9, r = d - cin*9;
        int kh = r / 3, kw = r - kh*3;
        int y = h + kh - 1, x = w + kw - 1;
        float v = 0.f;
        if (y >= 0 && y < HH && x >= 0 && x < WW)
            v = fmap[(((size_t)n*CINC + cin)*HH + y)*WW + x];
        sh[d] = v;
    }
    __syncthreads();

    int c = t & 63;            // channel (lane-contiguous -> coalesced Wt loads)
    int g = t >> 6;            // d-group 0..7
    float acc = 0.f;
    int d0 = g * 72;
    #pragma unroll 8
    for (int d = d0; d < d0 + 72; d++)
        acc = fmaf(sh[d], d_Wt[d*COUTC + c], acc);
    red[t] = acc;
    __syncthreads();

    if (t < COUTC) {
        float r = bias[t];
        #pragma unroll
        for (int g2 = 0; g2 < 8; g2++) r += red[t + g2*64];
        // quad layout: [n][c/4][bin][c%4]
        d_rep4[(((size_t)n*(COUTC/4) + (t >> 2))*MEM + b)*4 + (t & 3)] = r;
    }
}

// K4: gather + write. Each thread: one float4 pixel group, 8 output channels
// (2 channel-quads). One LDG.128 fetches 4 channels of one bin; populated bins
// cluster so each gather touches ~4 cache lines. 4x4 register transpose, then
// coalesced float4 stores.
__global__ void k_out(float* __restrict__ out) {
    int tid = blockIdx.x * blockDim.x + threadIdx.x;  // [0, NIMG*(COUTC/CG)*NP4)
    int q    = tid % NP4;
    int rest = tid / NP4;
    int cg   = rest % (COUTC/CG);
    int n    = rest / (COUTC/CG);
    int cq0  = cg * (CG/4);                // first channel-quad index

    int4 b4 = ((const int4*)d_bins)[n*NP4 + q];

    #pragma unroll
    for (int jq = 0; jq < CG/4; jq++) {
        const float4* rt = (const float4*)d_rep4 + ((size_t)n*(COUTC/4) + cq0 + jq)*MEM;
        float4 v0 = rt[b4.x];
        float4 v1 = rt[b4.y];
        float4 v2 = rt[b4.z];
        float4 v3 = rt[b4.w];
        int cbase = (cq0 + jq) * 4;
        float4* ob = (float4*)out + ((size_t)n*COUTC + cbase)*NP4 + q;
        ob[0*NP4] = make_float4(v0.x, v1.x, v2.x, v3.x);
        ob[1*NP4] = make_float4(v0.y, v1.y, v2.y, v3.y);
        ob[2*NP4] = make_float4(v0.z, v1.z, v2.z, v3.z);
        ob[3*NP4] = make_float4(v0.w, v1.w, v2.w, v3.w);
    }
}

extern "C" void kernel_launch(void* const* d_in, const int* in_sizes, int n_in,
                              void* d_out, int out_size) {
    const float* fmap   = (const float*)d_in[0];
    const float* weight = (const float*)d_in[1];
    const float* bias   = (const float*)d_in[2];
    float* out = (float*)d_out;

    (void)in_sizes; (void)n_in; (void)out_size;

    k_prep<<<(NIMG*NP4 + 127)/128, 128>>>(fmap, weight);   // 196 blocks
    k_bin <<<(NIMG*NP4 + 127)/128, 128>>>();               // 196 blocks
    dim3 repGrid(MEM, NIMG);
    k_rep<<<repGrid, 512>>>(fmap, bias);
    k_out<<<(NIMG*(COUTC/CG)*NP4 + 255)/256, 256>>>(out);  // 784 blocks
}

// round 9
// speedup vs baseline: 2.3977x; 1.0737x over previous
#include <cuda_runtime.h>

// Problem constants (static per reference)
#define NIMG 8
#define CINC 64
#define HH   112
#define WW   112
#define NP   (HH*WW)      // 12544 pixels/patches per image
#define NP4  (NP/4)       // 3136 float4 groups per image
#define COUTC 64
#define DD   576          // CIN*K*K
#define MEM  1025

// Scratch (device globals — no allocation allowed)
__device__ float d_S[NIMG*NP];                 // per-pixel channel sums
__device__ int   d_bins[NIMG*NP];              // bin per patch
__device__ int   d_first[NIMG*MEM];            // first-occurring patch idx per bin
__device__ float d_rep4[NIMG*(COUTC/4)*MEM*4]; // reps, quad layout: [n][c/4][bin][c%4]
__device__ float d_Wt[DD*COUTC];               // transposed weight: Wt[d*64 + c]

// K1: per-pixel channel sum (1 px/thread -> 100K threads, MLP-rich) + init
// first table + weight transpose. Per-pixel FP order: sequential c=0..63,
// single accumulator — bit-identical to all validated rounds.
__global__ void k_prep(const float* __restrict__ fmap,
                       const float* __restrict__ weight) {
    int tid   = blockIdx.x * blockDim.x + threadIdx.x;   // [0, NIMG*NP)
    int total = gridDim.x * blockDim.x;

    for (int i = tid; i < NIMG*MEM; i += total) d_first[i] = NP;

    for (int i = tid; i < COUTC*DD; i += total) {
        int c = i / DD, d = i - c*DD;
        d_Wt[d*COUTC + c] = weight[i];
    }

    int n = tid / NP, p = tid - n*NP;
    const float* base = fmap + (size_t)n * CINC * NP + p;
    float s = 0.f;
    #pragma unroll 16
    for (int c = 0; c < CINC; c++) s += base[c * NP];
    d_S[tid] = s;
}

// K2: 3x3 box sum (zero-padded) -> quantized bin -> scatter-min first.
// 1 px/thread. Per-pixel FP order: rows dy=-1,0,+1; within a row
// ((sum+left)+center)+right — identical to the validated interior pattern.
__global__ void k_bin() {
    int tid = blockIdx.x * blockDim.x + threadIdx.x;     // [0, NIMG*NP)
    int n = tid / NP, p = tid - n*NP;
    int h = p / WW, w = p - h*WW;
    const float* S = d_S + n*NP;

    float sum = 0.f;
    #pragma unroll
    for (int dy = -1; dy <= 1; dy++) {
        int y = h + dy;
        if (y < 0 || y >= HH) continue;
        const float* Sy = S + y*WW;
        if (w > 0)      sum += Sy[w - 1];
        sum += Sy[w];
        if (w < WW - 1) sum += Sy[w + 1];
    }

    float m = sum / (float)DD;
    int s = (int)(m * 100.0f);             // trunc toward zero == astype(int32)
    int b = s + 512;
    b = b < 0 ? 0 : (b > MEM-1 ? MEM-1 : b);
    d_bins[tid] = b;
    atomicMin(&d_first[n*MEM + b], p);
}

// K3: representative GEMVs, split-K. One block per (bin, image), 512 threads =
// 64 channels x 8 d-groups of 72. Only populated bins (~35/image) do work.
__global__ void __launch_bounds__(512) k_rep(const float* __restrict__ fmap,
                                             const float* __restrict__ bias) {
    int b = blockIdx.x, n = blockIdx.y;
    int p = d_first[n*MEM + b];
    if (p >= NP) return;                   // unused bin

    __shared__ float sh[DD];
    __shared__ float red[512];
    int t = threadIdx.x;
    int h = p / WW, w = p - h*WW;

    for (int d = t; d < DD; d += 512) {
        int cin = d / 9, r = d - cin*9;
        int kh = r / 3, kw = r - kh*3;
        int y = h + kh - 1, x = w + kw - 1;
        float v = 0.f;
        if (y >= 0 && y < HH && x >= 0 && x < WW)
            v = fmap[(((size_t)n*CINC + cin)*HH + y)*WW + x];
        sh[d] = v;
    }
    __syncthreads();

    int c = t & 63;            // channel (lane-contiguous -> coalesced Wt loads)
    int g = t >> 6;            // d-group 0..7
    float acc = 0.f;
    int d0 = g * 72;
    #pragma unroll 8
    for (int d = d0; d < d0 + 72; d++)
        acc = fmaf(sh[d], d_Wt[d*COUTC + c], acc);
    red[t] = acc;
    __syncthreads();

    if (t < COUTC) {
        float r = bias[t];
        #pragma unroll
        for (int g2 = 0; g2 < 8; g2++) r += red[t + g2*64];
        // quad layout: [n][c/4][bin][c%4]
        d_rep4[(((size_t)n*(COUTC/4) + (t >> 2))*MEM + b)*4 + (t & 3)] = r;
    }
}

// K4: gather + write. Each thread: one float4 pixel group, ONE channel-quad
// (CG=4). One LDG.128 fetches 4 channels of one bin; 4x4 register transpose,
// then coalesced float4 stores. 1568 blocks -> ~2x occupancy vs R4.
__global__ void k_out(float* __restrict__ out) {
    int tid = blockIdx.x * blockDim.x + threadIdx.x;  // [0, NIMG*16*NP4)
    int q    = tid % NP4;
    int rest = tid / NP4;
    int cq   = rest % (COUTC/4);
    int n    = rest / (COUTC/4);

    int4 b4 = ((const int4*)d_bins)[n*NP4 + q];

    const float4* rt = (const float4*)d_rep4 + ((size_t)n*(COUTC/4) + cq)*MEM;
    float4 v0 = rt[b4.x];
    float4 v1 = rt[b4.y];
    float4 v2 = rt[b4.z];
    float4 v3 = rt[b4.w];

    int cbase = cq * 4;
    float4* ob = (float4*)out + ((size_t)n*COUTC + cbase)*NP4 + q;
    ob[0*NP4] = make_float4(v0.x, v1.x, v2.x, v3.x);
    ob[1*NP4] = make_float4(v0.y, v1.y, v2.y, v3.y);
    ob[2*NP4] = make_float4(v0.z, v1.z, v2.z, v3.z);
    ob[3*NP4] = make_float4(v0.w, v1.w, v2.w, v3.w);
}

extern "C" void kernel_launch(void* const* d_in, const int* in_sizes, int n_in,
                              void* d_out, int out_size) {
    const float* fmap   = (const float*)d_in[0];
    const float* weight = (const float*)d_in[1];
    const float* bias   = (const float*)d_in[2];
    float* out = (float*)d_out;

    (void)in_sizes; (void)n_in; (void)out_size;

    k_prep<<<(NIMG*NP + 255)/256, 256>>>(fmap, weight);    // 392 blocks
    k_bin <<<(NIMG*NP + 255)/256, 256>>>();                // 392 blocks
    dim3 repGrid(MEM, NIMG);
    k_rep<<<repGrid, 512>>>(fmap, bias);
    k_out<<<(NIMG*(COUTC/4)*NP4 + 255)/256, 256>>>(out);   // 1568 blocks
}

// round 10
// speedup vs baseline: 2.6282x; 1.0962x over previous
#include <cuda_runtime.h>

// Problem constants (static per reference)
#define NIMG 8
#define CINC 64
#define HH   112
#define WW   112
#define NP   (HH*WW)      // 12544 pixels/patches per image
#define NP4  (NP/4)       // 3136 float4 groups per image
#define NP8  (NP4/2)      // 1568: two pixel-groups per k_out thread
#define COUTC 64
#define DD   576          // CIN*K*K
#define MEM  1025

// Scratch (device globals — no allocation allowed)
__device__ float d_S[NIMG*NP];                 // per-pixel channel sums
__device__ int   d_bins[NIMG*NP];              // bin per patch
__device__ int   d_first[NIMG*MEM];            // first-occurring patch idx per bin
__device__ float d_rep4[NIMG*(COUTC/4)*MEM*4]; // reps, quad layout: [n][c/4][bin][c%4]
__device__ float d_Wt[DD*COUTC];               // transposed weight: Wt[d*64 + c]
__device__ int   d_live[NIMG*MEM];             // compacted list of populated (n*MEM+b)
__device__ int   d_nlive;                      // count of populated bins

// K1: per-pixel channel sum (1 px/thread, MLP-rich) + init first table +
// weight transpose + live-count reset. Per-pixel FP order: sequential c=0..63,
// single accumulator — bit-identical to all validated rounds.
__global__ void k_prep(const float* __restrict__ fmap,
                       const float* __restrict__ weight) {
    int tid   = blockIdx.x * blockDim.x + threadIdx.x;   // [0, NIMG*NP)
    int total = gridDim.x * blockDim.x;

    if (tid == 0) d_nlive = 0;

    for (int i = tid; i < NIMG*MEM; i += total) d_first[i] = NP;

    for (int i = tid; i < COUTC*DD; i += total) {
        int c = i / DD, d = i - c*DD;
        d_Wt[d*COUTC + c] = weight[i];
    }

    int n = tid / NP, p = tid - n*NP;
    const float* base = fmap + (size_t)n * CINC * NP + p;
    float s = 0.f;
    #pragma unroll 16
    for (int c = 0; c < CINC; c++) s += base[c * NP];
    d_S[tid] = s;
}

// K2: 3x3 box sum (zero-padded) -> quantized bin -> scatter-min first.
// The unique thread that observes the pristine NP value appends the bin to
// the live list (exactly one winner per bin).
__global__ void k_bin() {
    int tid = blockIdx.x * blockDim.x + threadIdx.x;     // [0, NIMG*NP)
    int n = tid / NP, p = tid - n*NP;
    int h = p / WW, w = p - h*WW;
    const float* S = d_S + n*NP;

    float sum = 0.f;
    #pragma unroll
    for (int dy = -1; dy <= 1; dy++) {
        int y = h + dy;
        if (y < 0 || y >= HH) continue;
        const float* Sy = S + y*WW;
        if (w > 0)      sum += Sy[w - 1];
        sum += Sy[w];
        if (w < WW - 1) sum += Sy[w + 1];
    }

    float m = sum / (float)DD;
    int s = (int)(m * 100.0f);             // trunc toward zero == astype(int32)
    int b = s + 512;
    b = b < 0 ? 0 : (b > MEM-1 ? MEM-1 : b);
    d_bins[tid] = b;

    int pair = n*MEM + b;
    int old = atomicMin(&d_first[pair], p);
    if (old == NP) {
        int idx = atomicAdd(&d_nlive, 1);
        d_live[idx] = pair;
    }
}

// K3: representative GEMVs over the COMPACTED live list. Fixed 296-block grid
// strides the ~280 entries; 512 threads = 64 channels x 8 d-groups of 72.
__global__ void __launch_bounds__(512) k_rep(const float* __restrict__ fmap,
                                             const float* __restrict__ bias) {
    __shared__ float sh[DD];
    __shared__ float red[512];
    int t = threadIdx.x;
    int nlive = *(volatile int*)&d_nlive;

    for (int i = blockIdx.x; i < nlive; i += gridDim.x) {
        int pair = d_live[i];
        int n = pair / MEM, b = pair - n*MEM;
        int p = d_first[pair];
        int h = p / WW, w = p - h*WW;

        __syncthreads();                    // protect sh/red reuse across iterations
        for (int d = t; d < DD; d += 512) {
            int cin = d / 9, r = d - cin*9;
            int kh = r / 3, kw = r - kh*3;
            int y = h + kh - 1, x = w + kw - 1;
            float v = 0.f;
            if (y >= 0 && y < HH && x >= 0 && x < WW)
                v = fmap[(((size_t)n*CINC + cin)*HH + y)*WW + x];
            sh[d] = v;
        }
        __syncthreads();

        int c = t & 63;            // channel (lane-contiguous -> coalesced Wt loads)
        int g = t >> 6;            // d-group 0..7
        float acc = 0.f;
        int d0 = g * 72;
        #pragma unroll 8
        for (int d = d0; d < d0 + 72; d++)
            acc = fmaf(sh[d], d_Wt[d*COUTC + c], acc);
        red[t] = acc;
        __syncthreads();

        if (t < COUTC) {
            float r = bias[t];
            #pragma unroll
            for (int g2 = 0; g2 < 8; g2++) r += red[t + g2*64];
            // quad layout: [n][c/4][bin][c%4]
            d_rep4[(((size_t)n*(COUTC/4) + (t >> 2))*MEM + b)*4 + (t & 3)] = r;
        }
    }
}

// K4: gather + write. Each thread: TWO independent pixel-groups (q, q+NP8) of
// one channel-quad. Independent bins->gather->store chains double MLP.
__global__ void k_out(float* __restrict__ out) {
    int tid = blockIdx.x * blockDim.x + threadIdx.x;  // [0, NIMG*16*NP8)
    int q    = tid % NP8;
    int rest = tid / NP8;
    int cq   = rest % (COUTC/4);
    int n    = rest / (COUTC/4);

    int4 bA = ((const int4*)d_bins)[n*NP4 + q];
    int4 bB = ((const int4*)d_bins)[n*NP4 + q + NP8];

    const float4* rt = (const float4*)d_rep4 + ((size_t)n*(COUTC/4) + cq)*MEM;
    float4 a0 = rt[bA.x], a1 = rt[bA.y], a2 = rt[bA.z], a3 = rt[bA.w];
    float4 c0 = rt[bB.x], c1 = rt[bB.y], c2 = rt[bB.z], c3 = rt[bB.w];

    int cbase = cq * 4;
    float4* ob = (float4*)out + ((size_t)n*COUTC + cbase)*NP4 + q;
    ob[0*NP4]       = make_float4(a0.x, a1.x, a2.x, a3.x);
    ob[1*NP4]       = make_float4(a0.y, a1.y, a2.y, a3.y);
    ob[2*NP4]       = make_float4(a0.z, a1.z, a2.z, a3.z);
    ob[3*NP4]       = make_float4(a0.w, a1.w, a2.w, a3.w);
    ob[0*NP4 + NP8] = make_float4(c0.x, c1.x, c2.x, c3.x);
    ob[1*NP4 + NP8] = make_float4(c0.y, c1.y, c2.y, c3.y);
    ob[2*NP4 + NP8] = make_float4(c0.z, c1.z, c2.z, c3.z);
    ob[3*NP4 + NP8] = make_float4(c0.w, c1.w, c2.w, c3.w);
}

extern "C" void kernel_launch(void* const* d_in, const int* in_sizes, int n_in,
                              void* d_out, int out_size) {
    const float* fmap   = (const float*)d_in[0];
    const float* weight = (const float*)d_in[1];
    const float* bias   = (const float*)d_in[2];
    float* out = (float*)d_out;

    (void)in_sizes; (void)n_in; (void)out_size;

    k_prep<<<(NIMG*NP + 255)/256, 256>>>(fmap, weight);    // 392 blocks
    k_bin <<<(NIMG*NP + 255)/256, 256>>>();                // 392 blocks
    k_rep <<<296, 512>>>(fmap, bias);                      // strides live list
    k_out <<<(NIMG*(COUTC/4)*NP8 + 255)/256, 256>>>(out);  // 784 blocks
}